// round 13
// baseline (speedup 1.0000x reference)
#include <cuda_runtime.h>
#include <cuda_bf16.h>
#include <mma.h>
#include <cstdint>

using namespace nvcuda;
typedef unsigned int u32;
typedef __nv_bfloat16 bf16;

#define BB 128
#define TT 512
#define FF 128
#define UU 512
#define G3 1536
#define NCTA 128
#define NTHR 128

// SMEM byte offsets
#define OFF_WH   0            // weights hi: up to 1024*32*2 = 64KB
#define OFF_WL   65536        // weights lo
#define OFF_ACT  131072       // 2 buffers x (hi 12288 + lo 12288) = 49152
#define ACT_LD   48           // bf16 elems per act row (32 data + 16 pad)
#define OFF_SCRA 180224       // f32 [128][36] = 18432
#define OFF_SCRB 198656
#define SMEM_BYTES 217088

__device__ __align__(128) bf16 g_xhi[(size_t)TT * BB * FF];
__device__ __align__(128) bf16 g_xlo[(size_t)TT * BB * FF];
__device__ __align__(128) bf16 g_h1hi[2 * BB * UU];
__device__ __align__(128) bf16 g_h1lo[2 * BB * UU];
__device__ __align__(128) bf16 g_h2hi[2 * BB * UU];
__device__ __align__(128) bf16 g_h2lo[2 * BB * UU];
__device__ __align__(128) float g_head[64 * BB];
__device__ __align__(128) int  g_bar[TT + 4];

__device__ __forceinline__ float sigm(float v) { return 1.0f / (1.0f + __expf(-v)); }
__device__ __forceinline__ void cpa16(u32 d, const void* s) {
    asm volatile("cp.async.cg.shared.global [%0], [%1], 16;" :: "r"(d), "l"(s) : "memory");
}
__device__ __forceinline__ void grid_barrier(int* bars, int s) {
    __syncthreads();
    if (threadIdx.x == 0) {
        asm volatile("red.release.gpu.global.add.u32 [%0], 1;" :: "l"(bars + s) : "memory");
        int v;
        do { asm volatile("ld.acquire.gpu.global.u32 %0, [%1];" : "=r"(v) : "l"(bars + s) : "memory"); }
        while (v < NCTA);
        if (s >= 1)
            asm volatile("st.global.relaxed.gpu.u32 [%0], %1;" :: "l"(bars + s - 1), "r"(0) : "memory");
    }
    __syncthreads();
}

typedef wmma::fragment<wmma::matrix_a, 16, 16, 16, bf16, wmma::row_major> FragA;
typedef wmma::fragment<wmma::matrix_b, 16, 16, 16, bf16, wmma::row_major> FragB;
typedef wmma::fragment<wmma::accumulator, 16, 16, 16, float> FragC;

__global__ void __launch_bounds__(NTHR, 1) gru_wmma(
    const float* __restrict__ W1, const float* __restrict__ U1,
    const float* __restrict__ bi1, const float* __restrict__ br1,
    const float* __restrict__ W2, const float* __restrict__ U2,
    const float* __restrict__ bi2, const float* __restrict__ br2,
    const float* __restrict__ Wd, const float* __restrict__ bd,
    bf16* xhi, bf16* xlo, bf16* h1hi, bf16* h1lo, bf16* h2hi, bf16* h2lo,
    float* head, int* bars, float* out)
{
    extern __shared__ char smc[];
    u32 sb = (u32)__cvta_generic_to_shared(smc);
    bf16* wh = (bf16*)(smc + OFF_WH);
    bf16* wl = (bf16*)(smc + OFF_WL);
    float* scrA = (float*)(smc + OFF_SCRA);
    float* scrB = (float*)(smc + OFF_SCRB);

    const int tid = threadIdx.x, wid = tid >> 5;
    const int cta = blockIdx.x;
    const bool isL1 = cta < 64;
    const int ug = cta & 63;
    const int inK = isL1 ? FF : UU;        // input-part K rows
    const int Ktot = inK + UU;             // 640 / 1024
    const int inCh = inK / 32, nch = Ktot / 32;

    if (tid == 0)
        asm volatile("st.global.relaxed.gpu.u32 [%0], %1;" :: "l"(bars + TT + 2), "r"(0) : "memory");
    // zero own h slices (both parities, hi+lo); thread = batch
    {
        bf16* Hh = isL1 ? h1hi : h2hi;
        bf16* Hl = isL1 ? h1lo : h2lo;
        uint4 z4 = make_uint4(0, 0, 0, 0);
        for (int par = 0; par < 2; par++) {
            size_t o = ((size_t)par * BB + tid) * UU + ug * 8;
            *reinterpret_cast<uint4*>(Hh + o) = z4;
            *reinterpret_cast<uint4*>(Hl + o) = z4;
        }
    }
    // weights: cols 0..23 = gates (col = g*8+u), cols 24..31 zero
    {
        const float* WA = isL1 ? W1 : W2;
        const float* WB = isL1 ? U1 : U2;
        for (int idx = tid; idx < Ktot * 24; idx += NTHR) {
            int r = idx / 24, c = idx - r * 24;
            int gcol = (c >> 3) * UU + ug * 8 + (c & 7);
            float v = (r < inK) ? WA[(size_t)r * G3 + gcol] : WB[(size_t)(r - inK) * G3 + gcol];
            bf16 h = __float2bfloat16(v);
            wh[r * 32 + c] = h;
            wl[r * 32 + c] = __float2bfloat16(v - __bfloat162float(h));
        }
        for (int idx = tid; idx < Ktot * 8; idx += NTHR) {
            int r = idx / 8, c = 24 + (idx & 7);
            wh[r * 32 + c] = __float2bfloat16(0.f);
            wl[r * 32 + c] = __float2bfloat16(0.f);
        }
    }
    float bZ[8], bR[8], bHx[8], bHr[8], hold[8];
    {
        const float* bi = isL1 ? bi1 : bi2;
        const float* br = isL1 ? br1 : br2;
        #pragma unroll
        for (int u = 0; u < 8; u++) {
            int j = ug * 8 + u;
            bZ[u] = bi[j] + br[j];
            bR[u] = bi[UU + j] + br[UU + j];
            bHx[u] = bi[2 * UU + j];
            bHr[u] = br[2 * UU + j];
            hold[u] = 0.0f;
        }
    }
    __syncthreads();
    grid_barrier(bars, 0);

    #pragma unroll 1
    for (int t = 0; t <= TT; t++) {
        const bool act = isL1 ? (t < TT) : (t > 0);
        if (act) {
            const bf16 *SAh, *SAl, *SBh, *SBl;
            int strA;
            if (isL1) {
                SAh = xhi + (size_t)t * BB * FF; SAl = xlo + (size_t)t * BB * FF; strA = FF;
                SBh = h1hi + (size_t)(t & 1) * BB * UU; SBl = h1lo + (size_t)(t & 1) * BB * UU;
            } else {
                SAh = h1hi + (size_t)(t & 1) * BB * UU; SAl = h1lo + (size_t)(t & 1) * BB * UU; strA = UU;
                SBh = h2hi + (size_t)((t + 1) & 1) * BB * UU; SBl = h2lo + (size_t)((t + 1) & 1) * BB * UU;
            }
            auto cpc = [&](int i) {
                const bf16 *sh, *sl; int st, kb;
                if (i < inCh) { sh = SAh; sl = SAl; st = strA; kb = i; }
                else          { sh = SBh; sl = SBl; st = UU;  kb = i - inCh; }
                u32 dh = sb + OFF_ACT + (u32)(i & 1) * 24576u;
                #pragma unroll
                for (int q = 0; q < 4; q++) {
                    int g2 = tid + NTHR * q;          // 0..511
                    int b = g2 >> 2, s = g2 & 3;
                    u32 off = (u32)(b * 96 + s * 16);
                    cpa16(dh + off, sh + (size_t)b * st + kb * 32 + s * 8);
                    cpa16(dh + 12288u + off, sl + (size_t)b * st + kb * 32 + s * 8);
                }
                asm volatile("cp.async.commit_group;" ::: "memory");
            };

            FragC accA[2][2], accB[2][2];
            #pragma unroll
            for (int m = 0; m < 2; m++)
                #pragma unroll
                for (int n = 0; n < 2; n++) {
                    wmma::fill_fragment(accA[m][n], 0.0f);
                    wmma::fill_fragment(accB[m][n], 0.0f);
                }

            cpc(0);
            #pragma unroll 1
            for (int ch = 0; ch < nch; ch++) {
                asm volatile("cp.async.wait_group 0;" ::: "memory");
                __syncthreads();
                if (ch + 1 < nch) cpc(ch + 1);
                const bf16* Ah = (const bf16*)(smc + OFF_ACT + (ch & 1) * 24576);
                const bf16* Al = Ah + 6144;
                const bool inpart = (ch < inCh);
                #pragma unroll
                for (int kt = 0; kt < 2; kt++) {
                    int krow = ch * 32 + kt * 16;
                    FragA fah[2], fal[2];
                    FragB fbh[2], fbl[2];
                    #pragma unroll
                    for (int m = 0; m < 2; m++) {
                        const bf16* ap = Ah + (wid * 32 + m * 16) * ACT_LD + kt * 16;
                        const bf16* ap2 = Al + (wid * 32 + m * 16) * ACT_LD + kt * 16;
                        wmma::load_matrix_sync(fah[m], ap, ACT_LD);
                        wmma::load_matrix_sync(fal[m], ap2, ACT_LD);
                    }
                    #pragma unroll
                    for (int n = 0; n < 2; n++) {
                        wmma::load_matrix_sync(fbh[n], wh + krow * 32 + n * 16, 32);
                        wmma::load_matrix_sync(fbl[n], wl + krow * 32 + n * 16, 32);
                    }
                    #pragma unroll
                    for (int m = 0; m < 2; m++)
                        #pragma unroll
                        for (int n = 0; n < 2; n++) {
                            FragC* acc = inpart ? &accA[m][n] : &accB[m][n];
                            wmma::mma_sync(*acc, fah[m], fbh[n], *acc);
                            wmma::mma_sync(*acc, fah[m], fbl[n], *acc);
                            wmma::mma_sync(*acc, fal[m], fbh[n], *acc);
                        }
                }
            }

            // store accumulators, then per-batch gate math
            #pragma unroll
            for (int m = 0; m < 2; m++)
                #pragma unroll
                for (int n = 0; n < 2; n++) {
                    wmma::store_matrix_sync(scrA + (wid * 32 + m * 16) * 36 + n * 16,
                                            accA[m][n], 36, wmma::mem_row_major);
                    wmma::store_matrix_sync(scrB + (wid * 32 + m * 16) * 36 + n * 16,
                                            accB[m][n], 36, wmma::mem_row_major);
                }
            __syncthreads();

            bf16 nh[8], nl[8];
            const float* ra = scrA + tid * 36;
            const float* rb = scrB + tid * 36;
            #pragma unroll
            for (int u = 0; u < 8; u++) {
                float zv = sigm(ra[u] + rb[u] + bZ[u]);
                float rv = sigm(ra[8 + u] + rb[8 + u] + bR[u]);
                float cand = fmaxf(ra[16 + u] + bHx[u] + rv * (rb[16 + u] + bHr[u]), 0.0f);
                float hn = zv * hold[u] + (1.0f - zv) * cand;
                hold[u] = hn;
                nh[u] = __float2bfloat16(hn);
                nl[u] = __float2bfloat16(hn - __bfloat162float(nh[u]));
            }
            {
                int wpar = isL1 ? ((t + 1) & 1) : (t & 1);
                bf16* Dh = (isL1 ? h1hi : h2hi) + ((size_t)wpar * BB + tid) * UU + ug * 8;
                bf16* Dl = (isL1 ? h1lo : h2lo) + ((size_t)wpar * BB + tid) * UU + ug * 8;
                *reinterpret_cast<uint4*>(Dh) = *reinterpret_cast<uint4*>(nh);
                *reinterpret_cast<uint4*>(Dl) = *reinterpret_cast<uint4*>(nl);
            }
        }
        grid_barrier(bars, 1 + t);
    }

    // head: L2 CTAs hold h2(final) in regs -> partials -> CTA0 reduces
    if (!isL1) {
        float acc = 0.0f;
        #pragma unroll
        for (int u = 0; u < 8; u++)
            acc += hold[u] * __ldg(&Wd[ug * 8 + u]);
        head[ug * BB + tid] = acc;
    }
    grid_barrier(bars, TT + 2);
    if (cta == 0) {
        float acc = bd[0];
        #pragma unroll 8
        for (int c = 0; c < 64; c++)
            acc += head[c * BB + tid];
        out[tid] = acc;
    }
}

// x (B,T,F) fp32 -> (T,B,F) bf16 hi/lo
__global__ void prep_x(const float* __restrict__ x, bf16* __restrict__ xh, bf16* __restrict__ xl)
{
    const int t = blockIdx.x, bq = blockIdx.y;
    for (int idx = threadIdx.x; idx < 32 * FF; idx += 128) {
        int b = bq * 32 + (idx >> 7), f = idx & 127;
        float v = x[((size_t)b * TT + t) * FF + f];
        bf16 h = __float2bfloat16(v);
        size_t o = ((size_t)t * BB + b) * FF + f;
        xh[o] = h;
        xl[o] = __float2bfloat16(v - __bfloat162float(h));
    }
}

extern "C" void kernel_launch(void* const* d_in, const int* in_sizes, int n_in,
                              void* d_out, int out_size)
{
    const float* x   = (const float*)d_in[0];
    const float* W1  = (const float*)d_in[1];
    const float* U1  = (const float*)d_in[2];
    const float* bi1 = (const float*)d_in[3];
    const float* br1 = (const float*)d_in[4];
    const float* W2  = (const float*)d_in[5];
    const float* U2  = (const float*)d_in[6];
    const float* bi2 = (const float*)d_in[7];
    const float* br2 = (const float*)d_in[8];
    const float* Wd  = (const float*)d_in[9];
    const float* bd  = (const float*)d_in[10];
    float* out = (float*)d_out;

    bf16 *xh, *xl, *h1h, *h1l, *h2h, *h2l; float* hd; int* bars;
    cudaGetSymbolAddress((void**)&xh, g_xhi);
    cudaGetSymbolAddress((void**)&xl, g_xlo);
    cudaGetSymbolAddress((void**)&h1h, g_h1hi);
    cudaGetSymbolAddress((void**)&h1l, g_h1lo);
    cudaGetSymbolAddress((void**)&h2h, g_h2hi);
    cudaGetSymbolAddress((void**)&h2l, g_h2lo);
    cudaGetSymbolAddress((void**)&hd, g_head);
    cudaGetSymbolAddress((void**)&bars, g_bar);

    cudaFuncSetAttribute(gru_wmma, cudaFuncAttributeMaxDynamicSharedMemorySize, SMEM_BYTES);

    prep_x<<<dim3(TT, 4), 128>>>(x, xh, xl);
    gru_wmma<<<NCTA, NTHR, SMEM_BYTES>>>(W1, U1, bi1, br1, W2, U2, bi2, br2, Wd, bd,
                                         xh, xl, h1h, h1l, h2h, h2l, hd, bars, out);
}

// round 14
// speedup vs baseline: 1.0028x; 1.0028x over previous
#include <cuda_runtime.h>
#include <cuda_bf16.h>
#include <mma.h>
#include <cstdint>

using namespace nvcuda;
typedef unsigned int u32;
typedef __nv_bfloat16 bf16;

#define BB 128
#define TT 512
#define FF 128
#define UU 512
#define G3 1536
#define NCTA 128
#define NTHR 512

// SMEM byte offsets
#define OFF_WH   0            // weights hi: 1024*32*2 = 64KB max
#define OFF_WL   65536        // weights lo
#define OFF_ACT  131072       // 3 buffers x (hi 12288 + lo 12288) = 73728
#define ACT_LD   48           // bf16 elems per act row (32 data + 16 pad)
#define ABUFB    24576
#define OFF_SCRA OFF_ACT              // scratch overlays act bufs 0-1 (dead then)
#define OFF_SCRB (OFF_ACT + 18432)
#define SMEM_BYTES 204800

__device__ __align__(128) bf16 g_xhi[(size_t)TT * BB * FF];
__device__ __align__(128) bf16 g_xlo[(size_t)TT * BB * FF];
__device__ __align__(128) bf16 g_h1hi[2 * BB * UU];
__device__ __align__(128) bf16 g_h1lo[2 * BB * UU];
__device__ __align__(128) bf16 g_h2hi[2 * BB * UU];
__device__ __align__(128) bf16 g_h2lo[2 * BB * UU];
__device__ __align__(128) float g_head[64 * BB];
__device__ __align__(128) int  g_bar[TT + 4];

__device__ __forceinline__ float sigm(float v) { return 1.0f / (1.0f + __expf(-v)); }
__device__ __forceinline__ void cpa16(u32 d, const void* s) {
    asm volatile("cp.async.cg.shared.global [%0], [%1], 16;" :: "r"(d), "l"(s) : "memory");
}
__device__ __forceinline__ void grid_barrier(int* bars, int s) {
    __syncthreads();
    if (threadIdx.x == 0) {
        asm volatile("red.release.gpu.global.add.u32 [%0], 1;" :: "l"(bars + s) : "memory");
        int v;
        do { asm volatile("ld.acquire.gpu.global.u32 %0, [%1];" : "=r"(v) : "l"(bars + s) : "memory"); }
        while (v < NCTA);
        if (s >= 1)
            asm volatile("st.global.relaxed.gpu.u32 [%0], %1;" :: "l"(bars + s - 1), "r"(0) : "memory");
    }
    __syncthreads();
}

typedef wmma::fragment<wmma::matrix_a, 16, 16, 16, bf16, wmma::row_major> FragA;
typedef wmma::fragment<wmma::matrix_b, 16, 16, 16, bf16, wmma::row_major> FragB;
typedef wmma::fragment<wmma::accumulator, 16, 16, 16, float> FragC;

__global__ void __launch_bounds__(NTHR, 1) gru_wmma(
    const float* __restrict__ W1, const float* __restrict__ U1,
    const float* __restrict__ bi1, const float* __restrict__ br1,
    const float* __restrict__ W2, const float* __restrict__ U2,
    const float* __restrict__ bi2, const float* __restrict__ br2,
    const float* __restrict__ Wd, const float* __restrict__ bd,
    bf16* xhi, bf16* xlo, bf16* h1hi, bf16* h1lo, bf16* h2hi, bf16* h2lo,
    float* head, int* bars, float* out)
{
    extern __shared__ char smc[];
    u32 sb = (u32)__cvta_generic_to_shared(smc);
    bf16* wh = (bf16*)(smc + OFF_WH);
    bf16* wl = (bf16*)(smc + OFF_WL);
    float* scrA = (float*)(smc + OFF_SCRA);
    float* scrB = (float*)(smc + OFF_SCRB);

    const int tid = threadIdx.x, wid = tid >> 5;
    const int mt = wid & 7, nt = wid >> 3;     // warp tile coords
    const int cta = blockIdx.x;
    const bool isL1 = cta < 64;
    const int ug = cta & 63;
    const int inK = isL1 ? FF : UU;
    const int Ktot = inK + UU;
    const int inCh = inK / 32, nch = Ktot / 32;

    if (tid == 0)
        asm volatile("st.global.relaxed.gpu.u32 [%0], %1;" :: "l"(bars + TT + 2), "r"(0) : "memory");
    if (tid < BB) {
        bf16* Hh = isL1 ? h1hi : h2hi;
        bf16* Hl = isL1 ? h1lo : h2lo;
        uint4 z4 = make_uint4(0, 0, 0, 0);
        for (int par = 0; par < 2; par++) {
            size_t o = ((size_t)par * BB + tid) * UU + ug * 8;
            *reinterpret_cast<uint4*>(Hh + o) = z4;
            *reinterpret_cast<uint4*>(Hl + o) = z4;
        }
    }
    // weights: cols 0..23 = gates (col = g*8+u), cols 24..31 zero
    {
        const float* WA = isL1 ? W1 : W2;
        const float* WB = isL1 ? U1 : U2;
        for (int idx = tid; idx < Ktot * 24; idx += NTHR) {
            int r = idx / 24, c = idx - r * 24;
            int gcol = (c >> 3) * UU + ug * 8 + (c & 7);
            float v = (r < inK) ? WA[(size_t)r * G3 + gcol] : WB[(size_t)(r - inK) * G3 + gcol];
            bf16 h = __float2bfloat16(v);
            wh[r * 32 + c] = h;
            wl[r * 32 + c] = __float2bfloat16(v - __bfloat162float(h));
        }
        for (int idx = tid; idx < Ktot * 8; idx += NTHR) {
            int r = idx / 8, c = 24 + (idx & 7);
            wh[r * 32 + c] = __float2bfloat16(0.f);
            wl[r * 32 + c] = __float2bfloat16(0.f);
        }
    }
    float bZ[8], bR[8], bHx[8], bHr[8], hold[8];
    {
        const float* bi = isL1 ? bi1 : bi2;
        const float* br = isL1 ? br1 : br2;
        #pragma unroll
        for (int u = 0; u < 8; u++) {
            int j = ug * 8 + u;
            bZ[u] = bi[j] + br[j];
            bR[u] = bi[UU + j] + br[UU + j];
            bHx[u] = bi[2 * UU + j];
            bHr[u] = br[2 * UU + j];
            hold[u] = 0.0f;
        }
    }
    __syncthreads();
    grid_barrier(bars, 0);

    #pragma unroll 1
    for (int t = 0; t <= TT; t++) {
        const bool act = isL1 ? (t < TT) : (t > 0);
        if (act) {
            const bf16 *SAh, *SAl, *SBh, *SBl;
            int strA;
            if (isL1) {
                SAh = xhi + (size_t)t * BB * FF; SAl = xlo + (size_t)t * BB * FF; strA = FF;
                SBh = h1hi + (size_t)(t & 1) * BB * UU; SBl = h1lo + (size_t)(t & 1) * BB * UU;
            } else {
                SAh = h1hi + (size_t)(t & 1) * BB * UU; SAl = h1lo + (size_t)(t & 1) * BB * UU; strA = UU;
                SBh = h2hi + (size_t)((t + 1) & 1) * BB * UU; SBl = h2lo + (size_t)((t + 1) & 1) * BB * UU;
            }
            auto cpc = [&](int i) {
                const bf16 *sh, *sl; int st, kb;
                if (i < inCh) { sh = SAh; sl = SAl; st = strA; kb = i; }
                else          { sh = SBh; sl = SBl; st = UU;  kb = i - inCh; }
                u32 dh = sb + OFF_ACT + (u32)(i % 3) * ABUFB;
                int b = tid >> 2, s = tid & 3;          // 512 granules hi, 512 lo
                u32 off = (u32)(b * 96 + s * 16);
                cpa16(dh + off, sh + (size_t)b * st + kb * 32 + s * 8);
                cpa16(dh + 12288u + off, sl + (size_t)b * st + kb * 32 + s * 8);
                asm volatile("cp.async.commit_group;" ::: "memory");
            };

            FragC accA, accB;
            wmma::fill_fragment(accA, 0.0f);
            wmma::fill_fragment(accB, 0.0f);

            cpc(0);
            if (nch > 1) cpc(1);
            #pragma unroll 1
            for (int ch = 0; ch < nch; ch++) {
                if (ch < nch - 1) asm volatile("cp.async.wait_group 1;" ::: "memory");
                else              asm volatile("cp.async.wait_group 0;" ::: "memory");
                __syncthreads();
                if (ch + 2 < nch) cpc(ch + 2);
                const bf16* Ah = (const bf16*)(smc + OFF_ACT + (ch % 3) * ABUFB);
                const bf16* Al = Ah + 6144;
                FragC* acc = (ch < inCh) ? &accA : &accB;
                #pragma unroll
                for (int kt = 0; kt < 2; kt++) {
                    int krow = ch * 32 + kt * 16;
                    FragA fah, fal;
                    FragB fbh, fbl;
                    wmma::load_matrix_sync(fah, Ah + (mt * 16) * ACT_LD + kt * 16, ACT_LD);
                    wmma::load_matrix_sync(fal, Al + (mt * 16) * ACT_LD + kt * 16, ACT_LD);
                    wmma::load_matrix_sync(fbh, wh + krow * 32 + nt * 16, 32);
                    wmma::load_matrix_sync(fbl, wl + krow * 32 + nt * 16, 32);
                    wmma::mma_sync(*acc, fah, fbh, *acc);
                    wmma::mma_sync(*acc, fah, fbl, *acc);
                    wmma::mma_sync(*acc, fal, fbh, *acc);
                }
            }
            __syncthreads();   // all warps done reading act bufs before scratch overlay

            wmma::store_matrix_sync(scrA + (mt * 16) * 36 + nt * 16, accA, 36, wmma::mem_row_major);
            wmma::store_matrix_sync(scrB + (mt * 16) * 36 + nt * 16, accB, 36, wmma::mem_row_major);
            __syncthreads();

            if (tid < BB) {
                bf16 nh[8], nl[8];
                const float* ra = scrA + tid * 36;
                const float* rb = scrB + tid * 36;
                #pragma unroll
                for (int u = 0; u < 8; u++) {
                    float zv = sigm(ra[u] + rb[u] + bZ[u]);
                    float rv = sigm(ra[8 + u] + rb[8 + u] + bR[u]);
                    float cand = fmaxf(ra[16 + u] + bHx[u] + rv * (rb[16 + u] + bHr[u]), 0.0f);
                    float hn = zv * hold[u] + (1.0f - zv) * cand;
                    hold[u] = hn;
                    nh[u] = __float2bfloat16(hn);
                    nl[u] = __float2bfloat16(hn - __bfloat162float(nh[u]));
                }
                int wpar = isL1 ? ((t + 1) & 1) : (t & 1);
                bf16* Dh = (isL1 ? h1hi : h2hi) + ((size_t)wpar * BB + tid) * UU + ug * 8;
                bf16* Dl = (isL1 ? h1lo : h2lo) + ((size_t)wpar * BB + tid) * UU + ug * 8;
                *reinterpret_cast<uint4*>(Dh) = *reinterpret_cast<uint4*>(nh);
                *reinterpret_cast<uint4*>(Dl) = *reinterpret_cast<uint4*>(nl);
            }
        }
        grid_barrier(bars, 1 + t);
    }

    // head: L2 CTAs hold h2(final) in regs -> partials -> CTA0 reduces
    if (!isL1 && tid < BB) {
        float acc = 0.0f;
        #pragma unroll
        for (int u = 0; u < 8; u++)
            acc += hold[u] * __ldg(&Wd[ug * 8 + u]);
        head[ug * BB + tid] = acc;
    }
    grid_barrier(bars, TT + 2);
    if (cta == 0 && tid < BB) {
        float acc = bd[0];
        #pragma unroll 8
        for (int c = 0; c < 64; c++)
            acc += head[c * BB + tid];
        out[tid] = acc;
    }
}

// x (B,T,F) fp32 -> (T,B,F) bf16 hi/lo
__global__ void prep_x(const float* __restrict__ x, bf16* __restrict__ xh, bf16* __restrict__ xl)
{
    const int t = blockIdx.x, bq = blockIdx.y;
    for (int idx = threadIdx.x; idx < 32 * FF; idx += 128) {
        int b = bq * 32 + (idx >> 7), f = idx & 127;
        float v = x[((size_t)b * TT + t) * FF + f];
        bf16 h = __float2bfloat16(v);
        size_t o = ((size_t)t * BB + b) * FF + f;
        xh[o] = h;
        xl[o] = __float2bfloat16(v - __bfloat162float(h));
    }
}

extern "C" void kernel_launch(void* const* d_in, const int* in_sizes, int n_in,
                              void* d_out, int out_size)
{
    const float* x   = (const float*)d_in[0];
    const float* W1  = (const float*)d_in[1];
    const float* U1  = (const float*)d_in[2];
    const float* bi1 = (const float*)d_in[3];
    const float* br1 = (const float*)d_in[4];
    const float* W2  = (const float*)d_in[5];
    const float* U2  = (const float*)d_in[6];
    const float* bi2 = (const float*)d_in[7];
    const float* br2 = (const float*)d_in[8];
    const float* Wd  = (const float*)d_in[9];
    const float* bd  = (const float*)d_in[10];
    float* out = (float*)d_out;

    bf16 *xh, *xl, *h1h, *h1l, *h2h, *h2l; float* hd; int* bars;
    cudaGetSymbolAddress((void**)&xh, g_xhi);
    cudaGetSymbolAddress((void**)&xl, g_xlo);
    cudaGetSymbolAddress((void**)&h1h, g_h1hi);
    cudaGetSymbolAddress((void**)&h1l, g_h1lo);
    cudaGetSymbolAddress((void**)&h2h, g_h2hi);
    cudaGetSymbolAddress((void**)&h2l, g_h2lo);
    cudaGetSymbolAddress((void**)&hd, g_head);
    cudaGetSymbolAddress((void**)&bars, g_bar);

    cudaFuncSetAttribute(gru_wmma, cudaFuncAttributeMaxDynamicSharedMemorySize, SMEM_BYTES);

    prep_x<<<dim3(TT, 4), 128>>>(x, xh, xl);
    gru_wmma<<<NCTA, NTHR, SMEM_BYTES>>>(W1, U1, bi1, br1, W2, U2, bi2, br2, Wd, bd,
                                         xh, xl, h1h, h1l, h2h, h2l, hd, bars, out);
}